// round 4
// baseline (speedup 1.0000x reference)
#include <cuda_runtime.h>
#include <cuda_bf16.h>
#include <math.h>
#include <stddef.h>
#include <stdint.h>

// Problem constants
#define Bc 8
#define Tc 2048
#define Cc 1024
#define Hc 16
#define Nn 64
#define CHUNKc 256
#define NCHUNK (Tc / CHUNKc)
#define BT (Bc * Tc)                 // 16384
#define BTC ((size_t)Bc * Tc * Cc)   // 16,777,216
#define CC2 (Cc * Cc)                // 1,048,576
#define NCBH (NCHUNK * Bc * Hc)      // 1024 S/M tiles

// ---------------------------------------------------------------------------
// Scratch (device globals)
// ---------------------------------------------------------------------------
__device__ __nv_bfloat16 g_xrh[BTC], g_xrl[BTC];
__device__ __nv_bfloat16 g_xkh[BTC], g_xkl[BTC];
__device__ __nv_bfloat16 g_xvh[BTC], g_xvl[BTC];
__device__ __nv_bfloat16 g_rh[BTC], g_rl[BTC];
__device__ __nv_bfloat16 g_kh[BTC], g_kl[BTC];
__device__ __nv_bfloat16 g_vh[BTC], g_vl[BTC];
__device__ float g_y[BTC];
__device__ __nv_bfloat16 g_y2h[BTC], g_y2l[BTC];
__device__ float g_S[(size_t)NCBH * 4096];
__device__ __nv_bfloat16 g_Mh[(size_t)NCBH * 4096], g_Ml[(size_t)NCBH * 4096];
__device__ __nv_bfloat16 g_Wrh[CC2], g_Wrl[CC2];
__device__ __nv_bfloat16 g_Wkh[CC2], g_Wkl[CC2];
__device__ __nv_bfloat16 g_Wvh[CC2], g_Wvl[CC2];
__device__ __nv_bfloat16 g_Woh[CC2], g_Wol[CC2];

// ---------------------------------------------------------------------------
// Helpers (family-portable: cp.async / ldmatrix / mma.sync)
// ---------------------------------------------------------------------------
__device__ __forceinline__ uint32_t smem_u32(const void* p) {
    uint32_t a;
    asm("{ .reg .u64 t; cvta.to.shared.u64 t, %1; cvt.u32.u64 %0, t; }"
        : "=r"(a) : "l"(p));
    return a;
}

#define CP_ASYNC16(sa, gp) \
    asm volatile("cp.async.cg.shared.global [%0], [%1], 16;" :: "r"(sa), "l"(gp) : "memory")
#define CP_COMMIT() asm volatile("cp.async.commit_group;" ::: "memory")
#define CP_WAIT(n)  asm volatile("cp.async.wait_group %0;" :: "n"(n) : "memory")

#define LDSM4(r0, r1, r2, r3, a)                                              \
    asm volatile("ldmatrix.sync.aligned.m8n8.x4.shared.b16 {%0,%1,%2,%3}, [%4];" \
                 : "=r"(r0), "=r"(r1), "=r"(r2), "=r"(r3) : "r"(a))
#define LDSM4T(r0, r1, r2, r3, a)                                             \
    asm volatile("ldmatrix.sync.aligned.m8n8.x4.trans.shared.b16 {%0,%1,%2,%3}, [%4];" \
                 : "=r"(r0), "=r"(r1), "=r"(r2), "=r"(r3) : "r"(a))

#define MMA(c, a, b0_, b1_)                                                   \
    asm volatile("mma.sync.aligned.m16n8k16.row.col.f32.bf16.bf16.f32 "       \
                 "{%0,%1,%2,%3}, {%4,%5,%6,%7}, {%8,%9}, {%0,%1,%2,%3};"      \
                 : "+f"((c)[0]), "+f"((c)[1]), "+f"((c)[2]), "+f"((c)[3])     \
                 : "r"((a)[0]), "r"((a)[1]), "r"((a)[2]), "r"((a)[3]),        \
                   "r"(b0_), "r"(b1_))

__device__ __forceinline__ void split2(float f, __nv_bfloat16& h, __nv_bfloat16& l) {
    h = __float2bfloat16(f);
    l = __float2bfloat16(f - __bfloat162float(h));
}

// ---------------------------------------------------------------------------
// Kernel 1: volatility gating + time-shift + maa mixing -> bf16 hi/lo splits
// ---------------------------------------------------------------------------
__global__ __launch_bounds__(256) void prep_kernel(
    const float* __restrict__ x, const float* __restrict__ vol,
    const float* __restrict__ Wvol, const float* __restrict__ bvol,
    const float* __restrict__ mk, const float* __restrict__ mv,
    const float* __restrict__ mr)
{
    size_t idx = (size_t)blockIdx.x * 256 + threadIdx.x;
    int c = (int)(idx & (Cc - 1));
    size_t bt = idx >> 10;
    int t = (int)(bt & (Tc - 1));

    float wv = Wvol[c];
    float bb = bvol[c];
    float g = 1.0f / (1.0f + expf(-(vol[bt] * wv + bb)));
    float xc = x[idx] * g;

    float xp = 0.0f;
    if (t > 0) {
        float gp = 1.0f / (1.0f + expf(-(vol[bt - 1] * wv + bb)));
        xp = x[idx - Cc] * gp;
    }
    float xx = xp - xc;
    __nv_bfloat16 h, l;
    split2(xc + xx * mk[c], h, l); g_xkh[idx] = h; g_xkl[idx] = l;
    split2(xc + xx * mv[c], h, l); g_xvh[idx] = h; g_xvl[idx] = l;
    split2(xc + xx * mr[c], h, l); g_xrh[idx] = h; g_xrl[idx] = l;
}

// fp32 -> bf16 hi/lo split (weights)
__global__ __launch_bounds__(256) void conv_kernel(
    const float* __restrict__ src, __nv_bfloat16* __restrict__ hi,
    __nv_bfloat16* __restrict__ lo, int n)
{
    int i = blockIdx.x * 256 + threadIdx.x;
    if (i < n) {
        __nv_bfloat16 h, l;
        split2(src[i], h, l);
        hi[i] = h; lo[i] = l;
    }
}

// ---------------------------------------------------------------------------
// Kernel 2: GEMM  C = A * W^T  (bf16x3, mma.sync).  CTA tile 128x256, BK=32,
// 8 warps (2m x 4n), warp tile 64x64, 2-stage cp.async.
// Epilogue: either fp32 C, or bf16 hi/lo split pair (for r/k/v).
// ---------------------------------------------------------------------------
#define GK 1024
#define GN 1024
#define NKI (GK / 32)              // 32
#define TROW 80
#define A_TB (128 * TROW)          // 10240
#define B_TB (256 * TROW)          // 20480
#define STAGE_B (2 * A_TB + 2 * B_TB)  // 61440
#define SMEM_GEMM (2 * STAGE_B)        // 122880

__device__ __forceinline__ void gemm_load_stage(
    uint32_t sbase, const __nv_bfloat16* a0, const __nv_bfloat16* a1,
    const __nv_bfloat16* b0, const __nv_bfloat16* b1, int koff, int tid)
{
    // A tiles: 128 rows, 4x16B each; thread -> row tid>>1, chunks (tid&1)*2 +{0,1}
    {
        const int row = tid >> 1;
        const int cb = (tid & 1) * 2;
        uint32_t ro = sbase + row * TROW + cb * 16;
        const __nv_bfloat16* g0 = a0 + (size_t)row * GK + koff + cb * 8;
        const __nv_bfloat16* g1 = a1 + (size_t)row * GK + koff + cb * 8;
        CP_ASYNC16(ro, g0);             CP_ASYNC16(ro + 16, g0 + 8);
        CP_ASYNC16(ro + A_TB, g1);      CP_ASYNC16(ro + A_TB + 16, g1 + 8);
    }
    // B tiles: 256 rows, 4x16B each; thread -> row tid, chunks 0..3
    {
        const int row = tid;
        uint32_t ro = sbase + 2 * A_TB + row * TROW;
        const __nv_bfloat16* g0 = b0 + (size_t)row * GK + koff;
        const __nv_bfloat16* g1 = b1 + (size_t)row * GK + koff;
#pragma unroll
        for (int ch = 0; ch < 4; ch++) {
            CP_ASYNC16(ro + ch * 16, g0 + ch * 8);
            CP_ASYNC16(ro + B_TB + ch * 16, g1 + ch * 8);
        }
    }
}

__global__ __launch_bounds__(256)
void gemm_bf16x3(const __nv_bfloat16* __restrict__ Ah, const __nv_bfloat16* __restrict__ Al,
                 const __nv_bfloat16* __restrict__ Bh, const __nv_bfloat16* __restrict__ Bl,
                 float* __restrict__ Cf,
                 __nv_bfloat16* __restrict__ Ch, __nv_bfloat16* __restrict__ Cl)
{
    extern __shared__ __align__(16) char smem[];
    const uint32_t sb = smem_u32(smem);

    const int tid = threadIdx.x;
    const int wid = tid >> 5;
    const int lane = tid & 31;
    const int wm = wid >> 2;          // 0..1 -> m offset 64*wm
    const int wn = wid & 3;           // 0..3 -> n offset 64*wn
    const int bm = blockIdx.y * 128;
    const int bn = blockIdx.x * 256;

    const __nv_bfloat16* a0 = Ah + (size_t)bm * GK;
    const __nv_bfloat16* a1 = Al + (size_t)bm * GK;
    const __nv_bfloat16* b0 = Bh + (size_t)bn * GK;
    const __nv_bfloat16* b1 = Bl + (size_t)bn * GK;

    float acc[4][8][4];
#pragma unroll
    for (int i = 0; i < 4; i++)
#pragma unroll
        for (int j = 0; j < 8; j++)
#pragma unroll
            for (int q = 0; q < 4; q++) acc[i][j][q] = 0.0f;

    const int lr = lane & 15;
    const int lc = lane >> 4;

    gemm_load_stage(sb, a0, a1, b0, b1, 0, tid);
    CP_COMMIT();

    for (int kt = 0; kt < NKI; kt++) {
        const uint32_t cbase = sb + (kt & 1) * STAGE_B;
        if (kt + 1 < NKI) {
            gemm_load_stage(sb + ((kt + 1) & 1) * STAGE_B, a0, a1, b0, b1,
                            (kt + 1) * 32, tid);
            CP_COMMIT();
            CP_WAIT(1);
        } else {
            CP_WAIT(0);
        }
        __syncthreads();

        const uint32_t sAh = cbase;
        const uint32_t sAl = cbase + A_TB;
        const uint32_t sBh = cbase + 2 * A_TB;
        const uint32_t sBl = cbase + 2 * A_TB + B_TB;

#pragma unroll
        for (int ks = 0; ks < 2; ks++) {
            const uint32_t kb = ks * 32 + lc * 16;

            uint32_t ah[4][4], al[4][4];
#pragma unroll
            for (int am = 0; am < 4; am++) {
                uint32_t roff = (uint32_t)(wm * 64 + am * 16 + lr) * TROW + kb;
                LDSM4(ah[am][0], ah[am][1], ah[am][2], ah[am][3], sAh + roff);
                LDSM4(al[am][0], al[am][1], al[am][2], al[am][3], sAl + roff);
            }

#pragma unroll
            for (int p = 0; p < 4; p++) {
                uint32_t roff = (uint32_t)(wn * 64 + p * 16 + lr) * TROW + kb;
                uint32_t q0, q1, q2, q3, u0, u1, u2, u3;
                LDSM4(q0, q1, q2, q3, sBh + roff);
                LDSM4(u0, u1, u2, u3, sBl + roff);
#pragma unroll
                for (int am = 0; am < 4; am++) {
                    MMA(acc[am][2 * p],     ah[am], q0, q2);
                    MMA(acc[am][2 * p],     ah[am], u0, u2);
                    MMA(acc[am][2 * p],     al[am], q0, q2);
                    MMA(acc[am][2 * p + 1], ah[am], q1, q3);
                    MMA(acc[am][2 * p + 1], ah[am], u1, u3);
                    MMA(acc[am][2 * p + 1], al[am], q1, q3);
                }
            }
        }
        __syncthreads();
    }

    // epilogue
    const int g = lane >> 2;
    const int cc = (lane & 3) * 2;
#pragma unroll
    for (int am = 0; am < 4; am++)
#pragma unroll
        for (int nt = 0; nt < 8; nt++) {
            int row0 = bm + wm * 64 + am * 16 + g;
            int col = bn + wn * 64 + nt * 8 + cc;
            if (Cf) {
                *(float2*)(Cf + (size_t)row0 * GN + col) =
                    make_float2(acc[am][nt][0], acc[am][nt][1]);
                *(float2*)(Cf + (size_t)(row0 + 8) * GN + col) =
                    make_float2(acc[am][nt][2], acc[am][nt][3]);
            } else {
                __nv_bfloat16 h0, l0, h1, l1;
                split2(acc[am][nt][0], h0, l0);
                split2(acc[am][nt][1], h1, l1);
                *(__nv_bfloat162*)(Ch + (size_t)row0 * GN + col) = {h0, h1};
                *(__nv_bfloat162*)(Cl + (size_t)row0 * GN + col) = {l0, l1};
                split2(acc[am][nt][2], h0, l0);
                split2(acc[am][nt][3], h1, l1);
                *(__nv_bfloat162*)(Ch + (size_t)(row0 + 8) * GN + col) = {h0, h1};
                *(__nv_bfloat162*)(Cl + (size_t)(row0 + 8) * GN + col) = {l0, l1};
            }
        }
}

// ---------------------------------------------------------------------------
// Kernel 3a: S_c = K_c^T V_c per (chunk, b, h).  bf16x3 mma via ldmatrix.trans.
// grid (bh=128, c=8), 128 threads (4 warps), warp owns 16 S-rows.
// ---------------------------------------------------------------------------
#define TR2 144
#define S_TILE_B (128 * TR2)        // 18432
#define SMEM_S (4 * S_TILE_B)       // 73728

__global__ __launch_bounds__(128) void s_kernel()
{
    extern __shared__ __align__(16) char smem[];
    const uint32_t sb = smem_u32(smem);
    const uint32_t sKh = sb, sKl = sb + S_TILE_B;
    const uint32_t sVh = sb + 2 * S_TILE_B, sVl = sb + 3 * S_TILE_B;

    const int bh = blockIdx.x, c = blockIdx.y;
    const int b = bh >> 4, h = bh & 15;
    const int tid = threadIdx.x;
    const int wid = tid >> 5;
    const int lane = tid & 31;

    float acc[8][4];
#pragma unroll
    for (int j = 0; j < 8; j++)
#pragma unroll
        for (int q = 0; q < 4; q++) acc[j][q] = 0.0f;

    // trans-ldmatrix lane address components
    const int rA = ((lane >> 4) & 1) * 8 + (lane & 7);   // A pattern row
    const int cA = ((lane >> 3) & 1) * 16 + wid * 32;    // A pattern col byte
    const int rB = ((lane >> 3) & 1) * 8 + (lane & 7);   // B pattern row
    const int cB = ((lane >> 4) & 1) * 16;               // B pattern col byte

    for (int half = 0; half < 2; half++) {
        const size_t grow0 = (size_t)b * Tc + c * CHUNKc + half * 128;
        // load 128 rows x 64 bf16 of Kh,Kl,Vh,Vl  (row = tid, 8 chunks each)
        {
            const size_t goff = (grow0 + tid) * Cc + h * 64;
            uint32_t ro = tid * TR2;
#pragma unroll
            for (int ch = 0; ch < 8; ch++) {
                CP_ASYNC16(sKh + ro + ch * 16, g_kh + goff + ch * 8);
                CP_ASYNC16(sKl + ro + ch * 16, g_kl + goff + ch * 8);
                CP_ASYNC16(sVh + ro + ch * 16, g_vh + goff + ch * 8);
                CP_ASYNC16(sVl + ro + ch * 16, g_vl + goff + ch * 8);
            }
        }
        CP_COMMIT(); CP_WAIT(0);
        __syncthreads();

#pragma unroll
        for (int ts = 0; ts < 8; ts++) {
            const int t0 = ts * 16;
            uint32_t aoff = (uint32_t)(t0 + rA) * TR2 + cA;
            uint32_t ah[4], al[4];
            LDSM4T(ah[0], ah[1], ah[2], ah[3], sKh + aoff);
            LDSM4T(al[0], al[1], al[2], al[3], sKl + aoff);
#pragma unroll
            for (int p = 0; p < 4; p++) {
                uint32_t boff = (uint32_t)(t0 + rB) * TR2 + cB + p * 32;
                uint32_t q0, q1, q2, q3, u0, u1, u2, u3;
                LDSM4T(q0, q1, q2, q3, sVh + boff);
                LDSM4T(u0, u1, u2, u3, sVl + boff);
                MMA(acc[2 * p],     ah, q0, q1);
                MMA(acc[2 * p],     ah, u0, u1);
                MMA(acc[2 * p],     al, q0, q1);
                MMA(acc[2 * p + 1], ah, q2, q3);
                MMA(acc[2 * p + 1], ah, u2, u3);
                MMA(acc[2 * p + 1], al, q2, q3);
            }
        }
        __syncthreads();
    }

    // store S (fp32): warp rows [wid*16, wid*16+16)
    float* Sp = g_S + (((size_t)c * 128 + bh) << 12);
    const int r0 = wid * 16 + (lane >> 2);
#pragma unroll
    for (int ng = 0; ng < 8; ng++) {
        int col = ng * 8 + (lane & 3) * 2;
        *(float2*)(Sp + r0 * 64 + col) = make_float2(acc[ng][0], acc[ng][1]);
        *(float2*)(Sp + (r0 + 8) * 64 + col) = make_float2(acc[ng][2], acc[ng][3]);
    }
}

// ---------------------------------------------------------------------------
// Kernel 3b: serial scan  M_c = S_c + w * M_{c-1}, emit bf16 splits.
// ---------------------------------------------------------------------------
__global__ __launch_bounds__(256) void scan_kernel(const float* __restrict__ td)
{
    const int bh = blockIdx.x;
    const int h = bh & 15;
    const float w = expf(-expf(td[h]));
    const int tid = threadIdx.x;

    float m[16];
#pragma unroll
    for (int i = 0; i < 16; i++) m[i] = 0.0f;

    for (int c = 0; c < NCHUNK; c++) {
        const size_t base = ((size_t)c * 128 + bh) << 12;
#pragma unroll
        for (int i = 0; i < 16; i++) {
            int e = tid + i * 256;
            float s = g_S[base + e];
            m[i] = s + w * m[i];
            __nv_bfloat16 hh, ll;
            split2(m[i], hh, ll);
            g_Mh[base + e] = hh;
            g_Ml[base + e] = ll;
        }
    }
}

// ---------------------------------------------------------------------------
// Kernel 3c: y_c = w * R_c @ M_c.  grid (bh=128, c=8), 128 threads (4 warps),
// warp owns 64 t-rows. bf16x3 mma; M transposed via ldmatrix.trans.
// ---------------------------------------------------------------------------
#define R_TILE_B (256 * TR2)        // 36864
#define M_TILE_B (64 * TR2)         // 9216
#define SMEM_Y (2 * R_TILE_B + 2 * M_TILE_B)  // 92160

__global__ __launch_bounds__(128) void y_kernel(const float* __restrict__ td)
{
    extern __shared__ __align__(16) char smem[];
    const uint32_t sb = smem_u32(smem);
    const uint32_t sRh = sb, sRl = sb + R_TILE_B;
    const uint32_t sMh = sb + 2 * R_TILE_B, sMl = sb + 2 * R_TILE_B + M_TILE_B;

    const int bh = blockIdx.x, c = blockIdx.y;
    const int b = bh >> 4, h = bh & 15;
    const float w = expf(-expf(td[h]));
    const int tid = threadIdx.x;
    const int wid = tid >> 5;
    const int lane = tid & 31;

    // load R chunk (256 rows x 64 bf16, hi+lo): thread rows tid, tid+128
    {
        const size_t grow0 = (size_t)b * Tc + c * CHUNKc;
#pragma unroll
        for (int j = 0; j < 2; j++) {
            const int row = tid + j * 128;
            const size_t goff = (grow0 + row) * Cc + h * 64;
            uint32_t ro = row * TR2;
#pragma unroll
            for (int ch = 0; ch < 8; ch++) {
                CP_ASYNC16(sRh + ro + ch * 16, g_rh + goff + ch * 8);
                CP_ASYNC16(sRl + ro + ch * 16, g_rl + goff + ch * 8);
            }
        }
        // load M (64 rows x 64 bf16, hi+lo): row = tid&63, 4 chunks at (tid>>6)*4
        const size_t mbase = ((size_t)c * 128 + bh) << 12;
        const int mrow = tid & 63;
        const int hc = (tid >> 6) * 4;
        uint32_t ro = mrow * TR2 + hc * 16;
        const size_t mo = mbase + (size_t)mrow * 64 + hc * 8;
#pragma unroll
        for (int ch = 0; ch < 4; ch++) {
            CP_ASYNC16(sMh + ro + ch * 16, g_Mh + mo + ch * 8);
            CP_ASYNC16(sMl + ro + ch * 16, g_Ml + mo + ch * 8);
        }
    }
    CP_COMMIT(); CP_WAIT(0);
    __syncthreads();

    const int tb = wid * 64;
    const int lr = lane & 15;
    const int lc = lane >> 4;
    const int rB = ((lane >> 3) & 1) * 8 + (lane & 7);
    const int cB = ((lane >> 4) & 1) * 16;

    float acc[4][8][4];
#pragma unroll
    for (int i = 0; i < 4; i++)
#pragma unroll
        for (int j = 0; j < 8; j++)
#pragma unroll
            for (int q = 0; q < 4; q++) acc[i][j][q] = 0.0f;

#pragma unroll
    for (int kn = 0; kn < 4; kn++) {
        uint32_t ah[4][4], al[4][4];
#pragma unroll
        for (int am = 0; am < 4; am++) {
            uint32_t roff = (uint32_t)(tb + am * 16 + lr) * TR2 + lc * 16 + kn * 32;
            LDSM4(ah[am][0], ah[am][1], ah[am][2], ah[am][3], sRh + roff);
            LDSM4(al[am][0], al[am][1], al[am][2], al[am][3], sRl + roff);
        }
#pragma unroll
        for (int p = 0; p < 4; p++) {
            uint32_t boff = (uint32_t)(kn * 16 + rB) * TR2 + cB + p * 32;
            uint32_t q0, q1, q2, q3, u0, u1, u2, u3;
            LDSM4T(q0, q1, q2, q3, sMh + boff);
            LDSM4T(u0, u1, u2, u3, sMl + boff);
#pragma unroll
            for (int am = 0; am < 4; am++) {
                MMA(acc[am][2 * p],     ah[am], q0, q1);
                MMA(acc[am][2 * p],     ah[am], u0, u1);
                MMA(acc[am][2 * p],     al[am], q0, q1);
                MMA(acc[am][2 * p + 1], ah[am], q2, q3);
                MMA(acc[am][2 * p + 1], ah[am], u2, u3);
                MMA(acc[am][2 * p + 1], al[am], q2, q3);
            }
        }
    }

    // store y (fp32, scaled by w)
    const int g = lane >> 2;
    const int ccol = (lane & 3) * 2;
#pragma unroll
    for (int am = 0; am < 4; am++)
#pragma unroll
        for (int ng = 0; ng < 8; ng++) {
            int trow = c * CHUNKc + tb + am * 16 + g;
            size_t rg = (size_t)(b * Tc + trow) * Cc + h * 64 + ng * 8 + ccol;
            *(float2*)(g_y + rg) = make_float2(w * acc[am][ng][0], w * acc[am][ng][1]);
            *(float2*)(g_y + rg + 8 * Cc) = make_float2(w * acc[am][ng][2], w * acc[am][ng][3]);
        }
}

// ---------------------------------------------------------------------------
// Kernel 4: GroupNorm (H=16 groups of 64) -> bf16 hi/lo splits
// ---------------------------------------------------------------------------
__global__ __launch_bounds__(256) void gn_kernel(
    const float* __restrict__ gw, const float* __restrict__ gb)
{
    int g = blockIdx.x * 8 + (threadIdx.x >> 5);
    int lane = threadIdx.x & 31;
    size_t basei = (size_t)g * 64;
    float v0 = g_y[basei + lane];
    float v1 = g_y[basei + 32 + lane];
    float s = v0 + v1;
    float q = v0 * v0 + v1 * v1;
#pragma unroll
    for (int o = 16; o > 0; o >>= 1) {
        s += __shfl_xor_sync(0xffffffffu, s, o);
        q += __shfl_xor_sync(0xffffffffu, q, o);
    }
    float mean = s * (1.0f / 64.0f);
    float var = q * (1.0f / 64.0f) - mean * mean;
    float rstd = rsqrtf(var + 1e-5f);
    int h = g & 15;
    int cb = h * 64;
    __nv_bfloat16 hh, ll;
    split2((v0 - mean) * rstd * gw[cb + lane] + gb[cb + lane], hh, ll);
    g_y2h[basei + lane] = hh; g_y2l[basei + lane] = ll;
    split2((v1 - mean) * rstd * gw[cb + 32 + lane] + gb[cb + 32 + lane], hh, ll);
    g_y2h[basei + 32 + lane] = hh; g_y2l[basei + 32 + lane] = ll;
}

// ---------------------------------------------------------------------------
// Host launcher
// ---------------------------------------------------------------------------
extern "C" void kernel_launch(void* const* d_in, const int* in_sizes, int n_in,
                              void* d_out, int out_size)
{
    const float* x    = (const float*)d_in[0];
    const float* vol  = (const float*)d_in[1];
    const float* Wvol = (const float*)d_in[2];
    const float* bvol = (const float*)d_in[3];
    const float* mk   = (const float*)d_in[4];
    const float* mv   = (const float*)d_in[5];
    const float* mr   = (const float*)d_in[6];
    const float* td   = (const float*)d_in[7];
    const float* Wk   = (const float*)d_in[8];
    const float* Wv   = (const float*)d_in[9];
    const float* Wr   = (const float*)d_in[10];
    const float* Wo   = (const float*)d_in[11];
    const float* gw   = (const float*)d_in[12];
    const float* gb   = (const float*)d_in[13];
    float* out = (float*)d_out;

    __nv_bfloat16 *xrh, *xrl, *xkh, *xkl, *xvh, *xvl, *y2h, *y2l;
    __nv_bfloat16 *rh, *rl, *kh, *kl, *vh, *vl;
    __nv_bfloat16 *wrh, *wrl, *wkh, *wkl, *wvh, *wvl, *woh, *wol;
    cudaGetSymbolAddress((void**)&xrh, g_xrh); cudaGetSymbolAddress((void**)&xrl, g_xrl);
    cudaGetSymbolAddress((void**)&xkh, g_xkh); cudaGetSymbolAddress((void**)&xkl, g_xkl);
    cudaGetSymbolAddress((void**)&xvh, g_xvh); cudaGetSymbolAddress((void**)&xvl, g_xvl);
    cudaGetSymbolAddress((void**)&y2h, g_y2h); cudaGetSymbolAddress((void**)&y2l, g_y2l);
    cudaGetSymbolAddress((void**)&rh, g_rh); cudaGetSymbolAddress((void**)&rl, g_rl);
    cudaGetSymbolAddress((void**)&kh, g_kh); cudaGetSymbolAddress((void**)&kl, g_kl);
    cudaGetSymbolAddress((void**)&vh, g_vh); cudaGetSymbolAddress((void**)&vl, g_vl);
    cudaGetSymbolAddress((void**)&wrh, g_Wrh); cudaGetSymbolAddress((void**)&wrl, g_Wrl);
    cudaGetSymbolAddress((void**)&wkh, g_Wkh); cudaGetSymbolAddress((void**)&wkl, g_Wkl);
    cudaGetSymbolAddress((void**)&wvh, g_Wvh); cudaGetSymbolAddress((void**)&wvl, g_Wvl);
    cudaGetSymbolAddress((void**)&woh, g_Woh); cudaGetSymbolAddress((void**)&wol, g_Wol);

    // prep + weight splits
    prep_kernel<<<(unsigned)(BTC / 256), 256>>>(x, vol, Wvol, bvol, mk, mv, mr);
    conv_kernel<<<CC2 / 256, 256>>>(Wr, wrh, wrl, CC2);
    conv_kernel<<<CC2 / 256, 256>>>(Wk, wkh, wkl, CC2);
    conv_kernel<<<CC2 / 256, 256>>>(Wv, wvh, wvl, CC2);
    conv_kernel<<<CC2 / 256, 256>>>(Wo, woh, wol, CC2);

    // projections (r/k/v write bf16 splits directly)
    cudaFuncSetAttribute(gemm_bf16x3, cudaFuncAttributeMaxDynamicSharedMemorySize,
                         SMEM_GEMM);
    dim3 gg(GN / 256, BT / 128);
    gemm_bf16x3<<<gg, 256, SMEM_GEMM>>>(xrh, xrl, wrh, wrl, nullptr, rh, rl);
    gemm_bf16x3<<<gg, 256, SMEM_GEMM>>>(xkh, xkl, wkh, wkl, nullptr, kh, kl);
    gemm_bf16x3<<<gg, 256, SMEM_GEMM>>>(xvh, xvl, wvh, wvl, nullptr, vh, vl);

    // attention: S tiles -> scan -> y
    cudaFuncSetAttribute(s_kernel, cudaFuncAttributeMaxDynamicSharedMemorySize, SMEM_S);
    s_kernel<<<dim3(Bc * Hc, NCHUNK), 128, SMEM_S>>>();
    scan_kernel<<<Bc * Hc, 256>>>(td);
    cudaFuncSetAttribute(y_kernel, cudaFuncAttributeMaxDynamicSharedMemorySize, SMEM_Y);
    y_kernel<<<dim3(Bc * Hc, NCHUNK), 128, SMEM_Y>>>(td);

    // GroupNorm -> bf16 splits
    gn_kernel<<<(BT * Hc) / 8, 256>>>(gw, gb);

    // output projection (fp32 out)
    gemm_bf16x3<<<gg, 256, SMEM_GEMM>>>(y2h, y2l, woh, wol, out, nullptr, nullptr);
}

// round 5
// speedup vs baseline: 1.2186x; 1.2186x over previous
#include <cuda_runtime.h>
#include <cuda_bf16.h>
#include <math.h>
#include <stddef.h>
#include <stdint.h>

// Problem constants
#define Bc 8
#define Tc 2048
#define Cc 1024
#define Hc 16
#define Nn 64
#define CHUNKc 256
#define NCHUNK (Tc / CHUNKc)
#define BT (Bc * Tc)                 // 16384
#define BTC ((size_t)Bc * Tc * Cc)   // 16,777,216
#define CC2 (Cc * Cc)                // 1,048,576
#define NCBH (NCHUNK * Bc * Hc)      // 1024 S/M tiles

// ---------------------------------------------------------------------------
// Scratch (device globals)
// ---------------------------------------------------------------------------
__device__ __nv_bfloat16 g_xrh[BTC], g_xrl[BTC];
__device__ __nv_bfloat16 g_xkh[BTC], g_xkl[BTC];
__device__ __nv_bfloat16 g_xvh[BTC], g_xvl[BTC];
__device__ __nv_bfloat16 g_rh[BTC], g_rl[BTC];
__device__ __nv_bfloat16 g_kh[BTC], g_kl[BTC];
__device__ __nv_bfloat16 g_vh[BTC], g_vl[BTC];
__device__ float g_y[BTC];
__device__ __nv_bfloat16 g_y2h[BTC], g_y2l[BTC];
__device__ float g_S[(size_t)NCBH * 4096];
__device__ __nv_bfloat16 g_Mh[(size_t)NCBH * 4096], g_Ml[(size_t)NCBH * 4096];
__device__ __nv_bfloat16 g_Wrh[CC2], g_Wrl[CC2];
__device__ __nv_bfloat16 g_Wkh[CC2], g_Wkl[CC2];
__device__ __nv_bfloat16 g_Wvh[CC2], g_Wvl[CC2];
__device__ __nv_bfloat16 g_Woh[CC2], g_Wol[CC2];

// ---------------------------------------------------------------------------
// Helpers (family-portable: cp.async / ldmatrix / mma.sync)
// ---------------------------------------------------------------------------
__device__ __forceinline__ uint32_t smem_u32(const void* p) {
    uint32_t a;
    asm("{ .reg .u64 t; cvta.to.shared.u64 t, %1; cvt.u32.u64 %0, t; }"
        : "=r"(a) : "l"(p));
    return a;
}

#define CP_ASYNC16(sa, gp) \
    asm volatile("cp.async.cg.shared.global [%0], [%1], 16;" :: "r"(sa), "l"(gp) : "memory")
#define CP_COMMIT() asm volatile("cp.async.commit_group;" ::: "memory")
#define CP_WAIT(n)  asm volatile("cp.async.wait_group %0;" :: "n"(n) : "memory")

#define LDSM4(r0, r1, r2, r3, a)                                              \
    asm volatile("ldmatrix.sync.aligned.m8n8.x4.shared.b16 {%0,%1,%2,%3}, [%4];" \
                 : "=r"(r0), "=r"(r1), "=r"(r2), "=r"(r3) : "r"(a))
#define LDSM4T(r0, r1, r2, r3, a)                                             \
    asm volatile("ldmatrix.sync.aligned.m8n8.x4.trans.shared.b16 {%0,%1,%2,%3}, [%4];" \
                 : "=r"(r0), "=r"(r1), "=r"(r2), "=r"(r3) : "r"(a))

#define MMA(c, a, b0_, b1_)                                                   \
    asm volatile("mma.sync.aligned.m16n8k16.row.col.f32.bf16.bf16.f32 "       \
                 "{%0,%1,%2,%3}, {%4,%5,%6,%7}, {%8,%9}, {%0,%1,%2,%3};"      \
                 : "+f"((c)[0]), "+f"((c)[1]), "+f"((c)[2]), "+f"((c)[3])     \
                 : "r"((a)[0]), "r"((a)[1]), "r"((a)[2]), "r"((a)[3]),        \
                   "r"(b0_), "r"(b1_))

__device__ __forceinline__ void split2(float f, __nv_bfloat16& h, __nv_bfloat16& l) {
    h = __float2bfloat16(f);
    l = __float2bfloat16(f - __bfloat162float(h));
}

// ---------------------------------------------------------------------------
// Kernel 1: volatility gating + time-shift + maa mixing -> bf16 hi/lo splits
// ---------------------------------------------------------------------------
__global__ __launch_bounds__(256) void prep_kernel(
    const float* __restrict__ x, const float* __restrict__ vol,
    const float* __restrict__ Wvol, const float* __restrict__ bvol,
    const float* __restrict__ mk, const float* __restrict__ mv,
    const float* __restrict__ mr)
{
    size_t idx = (size_t)blockIdx.x * 256 + threadIdx.x;
    int c = (int)(idx & (Cc - 1));
    size_t bt = idx >> 10;
    int t = (int)(bt & (Tc - 1));

    float wv = Wvol[c];
    float bb = bvol[c];
    float g = 1.0f / (1.0f + expf(-(vol[bt] * wv + bb)));
    float xc = x[idx] * g;

    float xp = 0.0f;
    if (t > 0) {
        float gp = 1.0f / (1.0f + expf(-(vol[bt - 1] * wv + bb)));
        xp = x[idx - Cc] * gp;
    }
    float xx = xp - xc;
    __nv_bfloat16 h, l;
    split2(xc + xx * mk[c], h, l); g_xkh[idx] = h; g_xkl[idx] = l;
    split2(xc + xx * mv[c], h, l); g_xvh[idx] = h; g_xvl[idx] = l;
    split2(xc + xx * mr[c], h, l); g_xrh[idx] = h; g_xrl[idx] = l;
}

// fp32 -> bf16 hi/lo split (weights)
__global__ __launch_bounds__(256) void conv_kernel(
    const float* __restrict__ src, __nv_bfloat16* __restrict__ hi,
    __nv_bfloat16* __restrict__ lo, int n)
{
    int i = blockIdx.x * 256 + threadIdx.x;
    if (i < n) {
        __nv_bfloat16 h, l;
        split2(src[i], h, l);
        hi[i] = h; lo[i] = l;
    }
}

// ---------------------------------------------------------------------------
// Kernel 2: GEMM  C = A * W^T  (bf16x3, mma.sync).  CTA tile 128x128, BK=32,
// 8 warps (4m x 2n), warp tile 32x64 (acc=64 regs — no spills).
// 3-stage cp.async pipeline. Epilogue: fp32 OR bf16 hi/lo split pair.
// ---------------------------------------------------------------------------
#define GK 1024
#define GN 1024
#define NKI (GK / 32)              // 32
#define TROW 80                    // bytes per smem row (32 bf16 + 16B pad)
#define TILE_B (128 * TROW)        // 10240
#define STAGE_B (4 * TILE_B)       // Ah, Al, Bh, Bl = 40960
#define NSTAGE 3
#define SMEM_GEMM (NSTAGE * STAGE_B)   // 122880

__device__ __forceinline__ void gemm_load_stage(
    uint32_t sbase, const __nv_bfloat16* a0, const __nv_bfloat16* a1,
    const __nv_bfloat16* b0, const __nv_bfloat16* b1, int koff, int tid)
{
    const int row = tid >> 1;
    const int cb = (tid & 1) * 2;
    const __nv_bfloat16* srcs[4] = {a0, a1, b0, b1};
#pragma unroll
    for (int m = 0; m < 4; m++) {
        uint32_t ro = sbase + m * TILE_B + row * TROW;
        const __nv_bfloat16* g = srcs[m] + (size_t)row * GK + koff;
        CP_ASYNC16(ro + (cb + 0) * 16, g + (cb + 0) * 8);
        CP_ASYNC16(ro + (cb + 1) * 16, g + (cb + 1) * 8);
    }
}

__global__ __launch_bounds__(256)
void gemm_bf16x3(const __nv_bfloat16* __restrict__ Ah, const __nv_bfloat16* __restrict__ Al,
                 const __nv_bfloat16* __restrict__ Bh, const __nv_bfloat16* __restrict__ Bl,
                 float* __restrict__ Cf,
                 __nv_bfloat16* __restrict__ Ch, __nv_bfloat16* __restrict__ Cl)
{
    extern __shared__ __align__(16) char smem[];
    const uint32_t sb = smem_u32(smem);

    const int tid = threadIdx.x;
    const int wid = tid >> 5;
    const int lane = tid & 31;
    const int wm = wid >> 1;         // 0..3 -> m offset 32*wm
    const int wn = wid & 1;          // 0..1 -> n offset 64*wn
    const int bm = blockIdx.y * 128;
    const int bn = blockIdx.x * 128;

    const __nv_bfloat16* a0 = Ah + (size_t)bm * GK;
    const __nv_bfloat16* a1 = Al + (size_t)bm * GK;
    const __nv_bfloat16* b0 = Bh + (size_t)bn * GK;
    const __nv_bfloat16* b1 = Bl + (size_t)bn * GK;

    float acc[2][8][4];
#pragma unroll
    for (int i = 0; i < 2; i++)
#pragma unroll
        for (int j = 0; j < 8; j++)
#pragma unroll
            for (int q = 0; q < 4; q++) acc[i][j][q] = 0.0f;

    const int lr = lane & 15;
    const int lc = lane >> 4;

    // prologue: stages 0, 1
    gemm_load_stage(sb, a0, a1, b0, b1, 0, tid);
    CP_COMMIT();
    gemm_load_stage(sb + STAGE_B, a0, a1, b0, b1, 32, tid);
    CP_COMMIT();

    int buf = 0;
    for (int kt = 0; kt < NKI; kt++) {
        if (kt + 1 < NKI) { CP_WAIT(1); } else { CP_WAIT(0); }
        __syncthreads();

        const uint32_t cbase = sb + buf * STAGE_B;
        const uint32_t sAh = cbase;
        const uint32_t sAl = cbase + TILE_B;
        const uint32_t sBh = cbase + 2 * TILE_B;
        const uint32_t sBl = cbase + 3 * TILE_B;

#pragma unroll
        for (int ks = 0; ks < 2; ks++) {
            const uint32_t kb = ks * 32 + lc * 16;

            uint32_t ah[2][4], al[2][4];
#pragma unroll
            for (int am = 0; am < 2; am++) {
                uint32_t roff = (uint32_t)(wm * 32 + am * 16 + lr) * TROW + kb;
                LDSM4(ah[am][0], ah[am][1], ah[am][2], ah[am][3], sAh + roff);
                LDSM4(al[am][0], al[am][1], al[am][2], al[am][3], sAl + roff);
            }

#pragma unroll
            for (int p = 0; p < 4; p++) {
                uint32_t roff = (uint32_t)(wn * 64 + p * 16 + lr) * TROW + kb;
                uint32_t q0, q1, q2, q3, u0, u1, u2, u3;
                LDSM4(q0, q1, q2, q3, sBh + roff);
                LDSM4(u0, u1, u2, u3, sBl + roff);
#pragma unroll
                for (int am = 0; am < 2; am++) {
                    MMA(acc[am][2 * p],     ah[am], q0, q2);
                    MMA(acc[am][2 * p],     ah[am], u0, u2);
                    MMA(acc[am][2 * p],     al[am], q0, q2);
                    MMA(acc[am][2 * p + 1], ah[am], q1, q3);
                    MMA(acc[am][2 * p + 1], ah[am], u1, u3);
                    MMA(acc[am][2 * p + 1], al[am], q1, q3);
                }
            }
        }

        if (kt + 2 < NKI) {
            int nbuf = buf + 2; if (nbuf >= NSTAGE) nbuf -= NSTAGE;
            gemm_load_stage(sb + nbuf * STAGE_B, a0, a1, b0, b1, (kt + 2) * 32, tid);
            CP_COMMIT();
        }
        buf = (buf + 1 == NSTAGE) ? 0 : buf + 1;
    }

    // epilogue
    const int g = lane >> 2;
    const int cc = (lane & 3) * 2;
#pragma unroll
    for (int am = 0; am < 2; am++)
#pragma unroll
        for (int nt = 0; nt < 8; nt++) {
            int row0 = bm + wm * 32 + am * 16 + g;
            int col = bn + wn * 64 + nt * 8 + cc;
            if (Cf) {
                *(float2*)(Cf + (size_t)row0 * GN + col) =
                    make_float2(acc[am][nt][0], acc[am][nt][1]);
                *(float2*)(Cf + (size_t)(row0 + 8) * GN + col) =
                    make_float2(acc[am][nt][2], acc[am][nt][3]);
            } else {
                __nv_bfloat16 h0, l0, h1, l1;
                split2(acc[am][nt][0], h0, l0);
                split2(acc[am][nt][1], h1, l1);
                *(__nv_bfloat162*)(Ch + (size_t)row0 * GN + col) = {h0, h1};
                *(__nv_bfloat162*)(Cl + (size_t)row0 * GN + col) = {l0, l1};
                split2(acc[am][nt][2], h0, l0);
                split2(acc[am][nt][3], h1, l1);
                *(__nv_bfloat162*)(Ch + (size_t)(row0 + 8) * GN + col) = {h0, h1};
                *(__nv_bfloat162*)(Cl + (size_t)(row0 + 8) * GN + col) = {l0, l1};
            }
        }
}

// ---------------------------------------------------------------------------
// Kernel 3a: S_c = K_c^T V_c per (chunk, b, h).  bf16x3 mma via ldmatrix.trans.
// ---------------------------------------------------------------------------
#define TR2 144
#define S_TILE_B (128 * TR2)        // 18432
#define SMEM_S (4 * S_TILE_B)       // 73728

__global__ __launch_bounds__(128) void s_kernel()
{
    extern __shared__ __align__(16) char smem[];
    const uint32_t sb = smem_u32(smem);
    const uint32_t sKh = sb, sKl = sb + S_TILE_B;
    const uint32_t sVh = sb + 2 * S_TILE_B, sVl = sb + 3 * S_TILE_B;

    const int bh = blockIdx.x, c = blockIdx.y;
    const int b = bh >> 4, h = bh & 15;
    const int tid = threadIdx.x;
    const int wid = tid >> 5;
    const int lane = tid & 31;

    float acc[8][4];
#pragma unroll
    for (int j = 0; j < 8; j++)
#pragma unroll
        for (int q = 0; q < 4; q++) acc[j][q] = 0.0f;

    const int rA = ((lane >> 4) & 1) * 8 + (lane & 7);
    const int cA = ((lane >> 3) & 1) * 16 + wid * 32;
    const int rB = ((lane >> 3) & 1) * 8 + (lane & 7);
    const int cB = ((lane >> 4) & 1) * 16;

    for (int half = 0; half < 2; half++) {
        const size_t grow0 = (size_t)b * Tc + c * CHUNKc + half * 128;
        {
            const size_t goff = (grow0 + tid) * Cc + h * 64;
            uint32_t ro = tid * TR2;
#pragma unroll
            for (int ch = 0; ch < 8; ch++) {
                CP_ASYNC16(sKh + ro + ch * 16, g_kh + goff + ch * 8);
                CP_ASYNC16(sKl + ro + ch * 16, g_kl + goff + ch * 8);
                CP_ASYNC16(sVh + ro + ch * 16, g_vh + goff + ch * 8);
                CP_ASYNC16(sVl + ro + ch * 16, g_vl + goff + ch * 8);
            }
        }
        CP_COMMIT(); CP_WAIT(0);
        __syncthreads();

#pragma unroll
        for (int ts = 0; ts < 8; ts++) {
            const int t0 = ts * 16;
            uint32_t aoff = (uint32_t)(t0 + rA) * TR2 + cA;
            uint32_t ah[4], al[4];
            LDSM4T(ah[0], ah[1], ah[2], ah[3], sKh + aoff);
            LDSM4T(al[0], al[1], al[2], al[3], sKl + aoff);
#pragma unroll
            for (int p = 0; p < 4; p++) {
                uint32_t boff = (uint32_t)(t0 + rB) * TR2 + cB + p * 32;
                uint32_t q0, q1, q2, q3, u0, u1, u2, u3;
                LDSM4T(q0, q1, q2, q3, sVh + boff);
                LDSM4T(u0, u1, u2, u3, sVl + boff);
                MMA(acc[2 * p],     ah, q0, q1);
                MMA(acc[2 * p],     ah, u0, u1);
                MMA(acc[2 * p],     al, q0, q1);
                MMA(acc[2 * p + 1], ah, q2, q3);
                MMA(acc[2 * p + 1], ah, u2, u3);
                MMA(acc[2 * p + 1], al, q2, q3);
            }
        }
        __syncthreads();
    }

    float* Sp = g_S + (((size_t)c * 128 + bh) << 12);
    const int r0 = wid * 16 + (lane >> 2);
#pragma unroll
    for (int ng = 0; ng < 8; ng++) {
        int col = ng * 8 + (lane & 3) * 2;
        *(float2*)(Sp + r0 * 64 + col) = make_float2(acc[ng][0], acc[ng][1]);
        *(float2*)(Sp + (r0 + 8) * 64 + col) = make_float2(acc[ng][2], acc[ng][3]);
    }
}

// ---------------------------------------------------------------------------
// Kernel 3b: serial scan  M_c = S_c + w * M_{c-1}, emit bf16 splits.
// ---------------------------------------------------------------------------
__global__ __launch_bounds__(256) void scan_kernel(const float* __restrict__ td)
{
    const int bh = blockIdx.x;
    const int h = bh & 15;
    const float w = expf(-expf(td[h]));
    const int tid = threadIdx.x;

    float m[16];
#pragma unroll
    for (int i = 0; i < 16; i++) m[i] = 0.0f;

    for (int c = 0; c < NCHUNK; c++) {
        const size_t base = ((size_t)c * 128 + bh) << 12;
#pragma unroll
        for (int i = 0; i < 16; i++) {
            int e = tid + i * 256;
            float s = g_S[base + e];
            m[i] = s + w * m[i];
            __nv_bfloat16 hh, ll;
            split2(m[i], hh, ll);
            g_Mh[base + e] = hh;
            g_Ml[base + e] = ll;
        }
    }
}

// ---------------------------------------------------------------------------
// Kernel 3c: y_c = w * R_c @ M_c.
// ---------------------------------------------------------------------------
#define R_TILE_B (256 * TR2)        // 36864
#define M_TILE_B (64 * TR2)         // 9216
#define SMEM_Y (2 * R_TILE_B + 2 * M_TILE_B)  // 92160

__global__ __launch_bounds__(128) void y_kernel(const float* __restrict__ td)
{
    extern __shared__ __align__(16) char smem[];
    const uint32_t sb = smem_u32(smem);
    const uint32_t sRh = sb, sRl = sb + R_TILE_B;
    const uint32_t sMh = sb + 2 * R_TILE_B, sMl = sb + 2 * R_TILE_B + M_TILE_B;

    const int bh = blockIdx.x, c = blockIdx.y;
    const int b = bh >> 4, h = bh & 15;
    const float w = expf(-expf(td[h]));
    const int tid = threadIdx.x;
    const int wid = tid >> 5;
    const int lane = tid & 31;

    {
        const size_t grow0 = (size_t)b * Tc + c * CHUNKc;
#pragma unroll
        for (int j = 0; j < 2; j++) {
            const int row = tid + j * 128;
            const size_t goff = (grow0 + row) * Cc + h * 64;
            uint32_t ro = row * TR2;
#pragma unroll
            for (int ch = 0; ch < 8; ch++) {
                CP_ASYNC16(sRh + ro + ch * 16, g_rh + goff + ch * 8);
                CP_ASYNC16(sRl + ro + ch * 16, g_rl + goff + ch * 8);
            }
        }
        const size_t mbase = ((size_t)c * 128 + bh) << 12;
        const int mrow = tid & 63;
        const int hc = (tid >> 6) * 4;
        uint32_t ro = mrow * TR2 + hc * 16;
        const size_t mo = mbase + (size_t)mrow * 64 + hc * 8;
#pragma unroll
        for (int ch = 0; ch < 4; ch++) {
            CP_ASYNC16(sMh + ro + ch * 16, g_Mh + mo + ch * 8);
            CP_ASYNC16(sMl + ro + ch * 16, g_Ml + mo + ch * 8);
        }
    }
    CP_COMMIT(); CP_WAIT(0);
    __syncthreads();

    const int tb = wid * 64;
    const int lr = lane & 15;
    const int lc = lane >> 4;
    const int rB = ((lane >> 3) & 1) * 8 + (lane & 7);
    const int cB = ((lane >> 4) & 1) * 16;

    float acc[4][8][4];
#pragma unroll
    for (int i = 0; i < 4; i++)
#pragma unroll
        for (int j = 0; j < 8; j++)
#pragma unroll
            for (int q = 0; q < 4; q++) acc[i][j][q] = 0.0f;

#pragma unroll
    for (int kn = 0; kn < 4; kn++) {
        uint32_t ah[4][4], al[4][4];
#pragma unroll
        for (int am = 0; am < 4; am++) {
            uint32_t roff = (uint32_t)(tb + am * 16 + lr) * TR2 + lc * 16 + kn * 32;
            LDSM4(ah[am][0], ah[am][1], ah[am][2], ah[am][3], sRh + roff);
            LDSM4(al[am][0], al[am][1], al[am][2], al[am][3], sRl + roff);
        }
#pragma unroll
        for (int p = 0; p < 4; p++) {
            uint32_t boff = (uint32_t)(kn * 16 + rB) * TR2 + cB + p * 32;
            uint32_t q0, q1, q2, q3, u0, u1, u2, u3;
            LDSM4T(q0, q1, q2, q3, sMh + boff);
            LDSM4T(u0, u1, u2, u3, sMl + boff);
#pragma unroll
            for (int am = 0; am < 4; am++) {
                MMA(acc[am][2 * p],     ah[am], q0, q1);
                MMA(acc[am][2 * p],     ah[am], u0, u1);
                MMA(acc[am][2 * p],     al[am], q0, q1);
                MMA(acc[am][2 * p + 1], ah[am], q2, q3);
                MMA(acc[am][2 * p + 1], ah[am], u2, u3);
                MMA(acc[am][2 * p + 1], al[am], q2, q3);
            }
        }
    }

    const int g = lane >> 2;
    const int ccol = (lane & 3) * 2;
#pragma unroll
    for (int am = 0; am < 4; am++)
#pragma unroll
        for (int ng = 0; ng < 8; ng++) {
            int trow = c * CHUNKc + tb + am * 16 + g;
            size_t rg = (size_t)(b * Tc + trow) * Cc + h * 64 + ng * 8 + ccol;
            *(float2*)(g_y + rg) = make_float2(w * acc[am][ng][0], w * acc[am][ng][1]);
            *(float2*)(g_y + rg + 8 * Cc) = make_float2(w * acc[am][ng][2], w * acc[am][ng][3]);
        }
}

// ---------------------------------------------------------------------------
// Kernel 4: GroupNorm (H=16 groups of 64) -> bf16 hi/lo splits
// ---------------------------------------------------------------------------
__global__ __launch_bounds__(256) void gn_kernel(
    const float* __restrict__ gw, const float* __restrict__ gb)
{
    int g = blockIdx.x * 8 + (threadIdx.x >> 5);
    int lane = threadIdx.x & 31;
    size_t basei = (size_t)g * 64;
    float v0 = g_y[basei + lane];
    float v1 = g_y[basei + 32 + lane];
    float s = v0 + v1;
    float q = v0 * v0 + v1 * v1;
#pragma unroll
    for (int o = 16; o > 0; o >>= 1) {
        s += __shfl_xor_sync(0xffffffffu, s, o);
        q += __shfl_xor_sync(0xffffffffu, q, o);
    }
    float mean = s * (1.0f / 64.0f);
    float var = q * (1.0f / 64.0f) - mean * mean;
    float rstd = rsqrtf(var + 1e-5f);
    int h = g & 15;
    int cb = h * 64;
    __nv_bfloat16 hh, ll;
    split2((v0 - mean) * rstd * gw[cb + lane] + gb[cb + lane], hh, ll);
    g_y2h[basei + lane] = hh; g_y2l[basei + lane] = ll;
    split2((v1 - mean) * rstd * gw[cb + 32 + lane] + gb[cb + 32 + lane], hh, ll);
    g_y2h[basei + 32 + lane] = hh; g_y2l[basei + 32 + lane] = ll;
}

// ---------------------------------------------------------------------------
// Host launcher
// ---------------------------------------------------------------------------
extern "C" void kernel_launch(void* const* d_in, const int* in_sizes, int n_in,
                              void* d_out, int out_size)
{
    const float* x    = (const float*)d_in[0];
    const float* vol  = (const float*)d_in[1];
    const float* Wvol = (const float*)d_in[2];
    const float* bvol = (const float*)d_in[3];
    const float* mk   = (const float*)d_in[4];
    const float* mv   = (const float*)d_in[5];
    const float* mr   = (const float*)d_in[6];
    const float* td   = (const float*)d_in[7];
    const float* Wk   = (const float*)d_in[8];
    const float* Wv   = (const float*)d_in[9];
    const float* Wr   = (const float*)d_in[10];
    const float* Wo   = (const float*)d_in[11];
    const float* gw   = (const float*)d_in[12];
    const float* gb   = (const float*)d_in[13];
    float* out = (float*)d_out;

    __nv_bfloat16 *xrh, *xrl, *xkh, *xkl, *xvh, *xvl, *y2h, *y2l;
    __nv_bfloat16 *rh, *rl, *kh, *kl, *vh, *vl;
    __nv_bfloat16 *wrh, *wrl, *wkh, *wkl, *wvh, *wvl, *woh, *wol;
    cudaGetSymbolAddress((void**)&xrh, g_xrh); cudaGetSymbolAddress((void**)&xrl, g_xrl);
    cudaGetSymbolAddress((void**)&xkh, g_xkh); cudaGetSymbolAddress((void**)&xkl, g_xkl);
    cudaGetSymbolAddress((void**)&xvh, g_xvh); cudaGetSymbolAddress((void**)&xvl, g_xvl);
    cudaGetSymbolAddress((void**)&y2h, g_y2h); cudaGetSymbolAddress((void**)&y2l, g_y2l);
    cudaGetSymbolAddress((void**)&rh, g_rh); cudaGetSymbolAddress((void**)&rl, g_rl);
    cudaGetSymbolAddress((void**)&kh, g_kh); cudaGetSymbolAddress((void**)&kl, g_kl);
    cudaGetSymbolAddress((void**)&vh, g_vh); cudaGetSymbolAddress((void**)&vl, g_vl);
    cudaGetSymbolAddress((void**)&wrh, g_Wrh); cudaGetSymbolAddress((void**)&wrl, g_Wrl);
    cudaGetSymbolAddress((void**)&wkh, g_Wkh); cudaGetSymbolAddress((void**)&wkl, g_Wkl);
    cudaGetSymbolAddress((void**)&wvh, g_Wvh); cudaGetSymbolAddress((void**)&wvl, g_Wvl);
    cudaGetSymbolAddress((void**)&woh, g_Woh); cudaGetSymbolAddress((void**)&wol, g_Wol);

    // prep + weight splits
    prep_kernel<<<(unsigned)(BTC / 256), 256>>>(x, vol, Wvol, bvol, mk, mv, mr);
    conv_kernel<<<CC2 / 256, 256>>>(Wr, wrh, wrl, CC2);
    conv_kernel<<<CC2 / 256, 256>>>(Wk, wkh, wkl, CC2);
    conv_kernel<<<CC2 / 256, 256>>>(Wv, wvh, wvl, CC2);
    conv_kernel<<<CC2 / 256, 256>>>(Wo, woh, wol, CC2);

    // projections (r/k/v write bf16 splits directly)
    cudaFuncSetAttribute(gemm_bf16x3, cudaFuncAttributeMaxDynamicSharedMemorySize,
                         SMEM_GEMM);
    dim3 gg(GN / 128, BT / 128);
    gemm_bf16x3<<<gg, 256, SMEM_GEMM>>>(xrh, xrl, wrh, wrl, nullptr, rh, rl);
    gemm_bf16x3<<<gg, 256, SMEM_GEMM>>>(xkh, xkl, wkh, wkl, nullptr, kh, kl);
    gemm_bf16x3<<<gg, 256, SMEM_GEMM>>>(xvh, xvl, wvh, wvl, nullptr, vh, vl);

    // attention: S tiles -> scan -> y
    cudaFuncSetAttribute(s_kernel, cudaFuncAttributeMaxDynamicSharedMemorySize, SMEM_S);
    s_kernel<<<dim3(Bc * Hc, NCHUNK), 128, SMEM_S>>>();
    scan_kernel<<<Bc * Hc, 256>>>(td);
    cudaFuncSetAttribute(y_kernel, cudaFuncAttributeMaxDynamicSharedMemorySize, SMEM_Y);
    y_kernel<<<dim3(Bc * Hc, NCHUNK), 128, SMEM_Y>>>(td);

    // GroupNorm -> bf16 splits
    gn_kernel<<<(BT * Hc) / 8, 256>>>(gw, gb);

    // output projection (fp32 out)
    gemm_bf16x3<<<gg, 256, SMEM_GEMM>>>(y2h, y2l, woh, wol, out, nullptr, nullptr);
}